// round 4
// baseline (speedup 1.0000x reference)
#include <cuda_runtime.h>
#include <cstdint>

// Problem constants
#define Bc 4
#define Nn 4096
#define Ff 64
#define ISPLIT 64         // i-range splits for colsum (per batch)
#define TI 128            // i-rows per block in k_main
#define JC 64             // k-chunk (j columns) per stage
#define KSPLIT 8
#define CPB (Nn / JC / KSPLIT)   // 8 chunks per block
#define LOG2E 1.4426950408889634f
#define C08L  (0.8f * LOG2E)

// ---------------- scratch (device globals; no allocation allowed) ----------
__device__ float g_h   [Bc * Nn * Ff];      // h = inp @ W
__device__ float g_hsP [Bc * 64 * 4096];    // packed tf32 hs per chunk (seg layout)
__device__ float g_fsrc[Bc * Nn];           // 0.2*log2e * f_src (per i)
__device__ float g_fdst[Bc * Nn];           // 0.2*log2e * f_dst (per j)
__device__ float g_part[ISPLIT][Bc * Nn];   // colsum partials
__device__ float g_fbf [Bc * Nn];           // 1.0 if colsum==0 else 0.0
__device__ float g_pout[KSPLIT][Bc * Nn * Ff]; // k-split partial outputs

// ---------------- helpers ---------------------------------------------------
__device__ __forceinline__ float ex2f(float x) {
    float r; asm("ex2.approx.f32 %0, %1;" : "=f"(r) : "f"(x)); return r;
}
__device__ __forceinline__ uint32_t f2tf32(float x) {
    uint32_t u; asm("cvt.rna.tf32.f32 %0, %1;" : "=r"(u) : "f"(x)); return u;
}
__device__ __forceinline__ uint32_t smem_u32(const void* p) {
    uint32_t a;
    asm("{ .reg .u64 t; cvta.to.shared.u64 t, %1; cvt.u32.u64 %0, t; }" : "=r"(a) : "l"(p));
    return a;
}
#define CPA16(dst, src) \
    asm volatile("cp.async.cg.shared.global [%0], [%1], 16;" :: "r"(dst), "l"(src))
#define MMA_TF32(c, a, b0, b1) \
    asm volatile("mma.sync.aligned.m16n8k8.row.col.f32.tf32.tf32.f32 " \
        "{%0,%1,%2,%3},{%4,%5,%6,%7},{%8,%9},{%0,%1,%2,%3};" \
        : "+f"((c)[0]), "+f"((c)[1]), "+f"((c)[2]), "+f"((c)[3]) \
        : "r"((a)[0]), "r"((a)[1]), "r"((a)[2]), "r"((a)[3]), "r"(b0), "r"(b1))

// smem byte offsets (dynamic smem, 16B aligned)
#define SM_ADJ   0u                    // 2 x 128*68*4 = 69632
#define SM_HS    69632u                // 2 x 256*20*4 = 40960
#define SM_DJ    110592u               // 2 x 256
#define SM_FB    111104u               // 2 x 256
#define SM_TOTAL 111616u

// ============================================================================
// Kernel 1: h = inp @ W ; fsrc/fdst = 0.2*log2e * (lrelu(h) @ a halves)
// ============================================================================
__global__ __launch_bounds__(256) void k_prep(const float* __restrict__ inp,
                                              const float* __restrict__ W,
                                              const float* __restrict__ a) {
    __shared__ float Ws[64 * 64];
    __shared__ float as[128];
    __shared__ float inps[4][64];
    __shared__ float redS[4][2], redD[4][2];

    const int t = threadIdx.x;
    const int rowBase = blockIdx.x * 4;

    #pragma unroll
    for (int k = 0; k < 16; ++k) Ws[t + k * 256] = W[t + k * 256];
    if (t < 128) as[t] = a[t];

    const int r = t >> 6;
    const int o = t & 63;
    inps[r][o] = inp[(size_t)(rowBase + r) * 64 + o];
    __syncthreads();

    float hv = 0.f;
    #pragma unroll
    for (int f = 0; f < 64; ++f) hv = fmaf(inps[r][f], Ws[f * 64 + o], hv);

    const int gRow = rowBase + r;
    g_h[(size_t)gRow * 64 + o] = hv;

    const float lh = hv > 0.f ? hv : 0.2f * hv;
    float ps = lh * as[o];
    float pd = lh * as[64 + o];
    #pragma unroll
    for (int off = 16; off > 0; off >>= 1) {
        ps += __shfl_xor_sync(0xffffffffu, ps, off);
        pd += __shfl_xor_sync(0xffffffffu, pd, off);
    }
    const int wh = (t >> 5) & 1;
    if ((t & 31) == 0) { redS[r][wh] = ps; redD[r][wh] = pd; }
    __syncthreads();
    if ((t & 63) == 0) {
        g_fsrc[gRow] = 0.2f * LOG2E * (redS[r][0] + redS[r][1]);
        g_fdst[gRow] = 0.2f * LOG2E * (redD[r][0] + redD[r][1]);
    }
}

// ============================================================================
// Kernel 2: colsum partials for ONE batch. p_ij = (t>0 ? 2^t : 0)
// grid (Nn/1024, ISPLIT), 256 thr; also primes L2 with this batch's adj slice.
// ============================================================================
__global__ __launch_bounds__(256) void k_colsum(const float* __restrict__ adj, int b) {
    const int j  = (blockIdx.x * 256 + threadIdx.x) * 4;
    const int i0 = blockIdx.y * (Nn / ISPLIT);
    const float4 dj = *(const float4*)(g_fdst + b * Nn + j);
    const float* __restrict__ fs = g_fsrc + b * Nn + i0;
    const float* __restrict__ ap = adj + ((size_t)b * Nn + i0) * Nn + j;

    float4 sum = make_float4(0.f, 0.f, 0.f, 0.f);
    #pragma unroll 8
    for (int i = 0; i < Nn / ISPLIT; ++i) {
        const float ci = fs[i];
        const float4 a = *(const float4*)(ap + (size_t)i * Nn);
        float t0 = fmaf(C08L, a.x, ci + dj.x);
        float t1 = fmaf(C08L, a.y, ci + dj.y);
        float t2 = fmaf(C08L, a.z, ci + dj.z);
        float t3 = fmaf(C08L, a.w, ci + dj.w);
        if (t0 > 0.f) sum.x += ex2f(t0);
        if (t1 > 0.f) sum.y += ex2f(t1);
        if (t2 > 0.f) sum.z += ex2f(t2);
        if (t3 > 0.f) sum.w += ex2f(t3);
    }
    *(float4*)(&g_part[blockIdx.y][b * Nn + j]) = sum;
}

// ============================================================================
// Kernel 3: reduce partials; pack hs = h/colsum (tf32) into B-fragment layout.
// One batch per launch. grid (64).
// ============================================================================
__global__ __launch_bounds__(256) void k_hpack(int b) {
    __shared__ float sc[64];
    const int t = threadIdx.x;
    const int c = blockIdx.x;
    const int j0 = c * 64;

    if (t < 64) {
        float cs = 0.f;
        #pragma unroll
        for (int s = 0; s < ISPLIT; ++s) cs += g_part[s][b * Nn + j0 + t];
        sc[t] = cs > 0.f ? (1.f / cs) : (1.f / (float)Nn);
        g_fbf[b * Nn + j0 + t] = cs > 0.f ? 0.f : 1.f;
    }
    __syncthreads();

    float* __restrict__ dst = g_hsP + (size_t)(b * 64 + c) * 4096;
    #pragma unroll
    for (int r = 0; r < 16; ++r) {
        const int o = t + r * 256;
        const int s = o >> 4, i = o & 15;
        const int ks = s >> 5, n07 = (s >> 2) & 7, k3 = s & 3;
        const int nt = i >> 1, half = i & 1;
        const int jl = ks * 8 + k3 + 4 * half;
        const int f  = nt * 8 + n07;
        const float v = g_h[((size_t)(b * Nn) + j0 + jl) * 64 + f] * sc[jl];
        dst[o] = __uint_as_float(f2tf32(v));
    }
}

// ============================================================================
// Kernel 4 (hot): partial out = A_att @ hs via mma.sync tf32, k-split.
// One batch per launch. grid (Nn/TI, KSPLIT), 128 thr (4 warps x 32 rows).
// ============================================================================
__device__ __forceinline__ void issue_chunk(uint32_t sm, int p,
                                            const float* __restrict__ adjB,
                                            const float* __restrict__ hsPb,
                                            const float* __restrict__ djB,
                                            const float* __restrict__ fbB,
                                            int cglob, int t) {
    const int j0 = cglob * JC;
    // adj tile: 128 rows x 64 cols, pad 68 floats (272B/row)
    const uint32_t adst = sm + SM_ADJ + (uint32_t)p * 34816u;
    #pragma unroll
    for (int q = 0; q < 16; ++q) {
        const int quad = t + q * 128;
        const int row = quad >> 4, c4 = quad & 15;
        CPA16(adst + (uint32_t)row * 272u + (uint32_t)c4 * 16u,
              adjB + (size_t)row * Nn + j0 + c4 * 4);
    }
    // hs packed: 256 segs x 16 floats, seg stride 20 floats (80B)
    const uint32_t hdst = sm + SM_HS + (uint32_t)p * 20480u;
    const float* __restrict__ hsrc = hsPb + (size_t)cglob * 4096;
    #pragma unroll
    for (int q = 0; q < 8; ++q) {
        const int quad = t + q * 128;
        const int s = quad >> 2, v = quad & 3;
        CPA16(hdst + (uint32_t)s * 80u + (uint32_t)v * 16u, hsrc + quad * 4);
    }
    if (t < 16)
        CPA16(sm + SM_DJ + (uint32_t)p * 256u + (uint32_t)t * 16u, djB + j0 + t * 4);
    else if (t < 32)
        CPA16(sm + SM_FB + (uint32_t)p * 256u + (uint32_t)(t - 16) * 16u,
              fbB + j0 + (t - 16) * 4);
}

__global__ __launch_bounds__(128) void k_main(const float* __restrict__ adj, int b) {
    extern __shared__ char dsm[];
    const uint32_t sm = smem_u32(dsm);

    const int t    = threadIdx.x;
    const int wid  = t >> 5;
    const int lane = t & 31;
    const int lq   = lane >> 2;   // group id (0..7)
    const int lm   = lane & 3;    // thread-in-group
    const int i0   = blockIdx.x * TI;
    const int ks   = blockIdx.y;
    const int c0g  = ks * CPB;    // first global chunk

    const float* __restrict__ adjB = adj + ((size_t)b * Nn + i0) * Nn;
    const float* __restrict__ hsPb = g_hsP + (size_t)b * 64 * 4096;
    const float* __restrict__ djB  = g_fdst + b * Nn;
    const float* __restrict__ fbB  = g_fbf  + b * Nn;

    // ci (pre-scaled by 0.2*log2e): rows 32*wid + 16*mt + 8*sel + lq
    float cil[4];
    #pragma unroll
    for (int k = 0; k < 4; ++k)
        cil[k] = g_fsrc[b * Nn + i0 + wid * 32 + (k >> 1) * 16 + (k & 1) * 8 + lq];

    float acc[2][8][4];
    #pragma unroll
    for (int mt = 0; mt < 2; ++mt)
        #pragma unroll
        for (int nt = 0; nt < 8; ++nt)
            #pragma unroll
            for (int q = 0; q < 4; ++q) acc[mt][nt][q] = 0.f;

    issue_chunk(sm, 0, adjB, hsPb, djB, fbB, c0g, t);
    asm volatile("cp.async.commit_group;" ::: "memory");

    const uint32_t adjW = sm + SM_ADJ + (uint32_t)(wid * 32) * 272u;

    for (int c = 0; c < CPB; ++c) {
        const int p = c & 1;
        if (c + 1 < CPB)
            issue_chunk(sm, p ^ 1, adjB, hsPb, djB, fbB, c0g + c + 1, t);
        asm volatile("cp.async.commit_group;" ::: "memory");
        asm volatile("cp.async.wait_group 1;" ::: "memory");
        __syncthreads();

        const uint32_t adjb = adjW + (uint32_t)p * 34816u;
        const uint32_t hsb  = sm + SM_HS + (uint32_t)p * 20480u;
        const float* djS = (const float*)(dsm + SM_DJ + p * 256);
        const float* fbS = (const float*)(dsm + SM_FB + p * 256);

        #pragma unroll
        for (int kk = 0; kk < 8; ++kk) {
            const float dj0 = djS[kk * 8 + lm];
            const float dj4 = djS[kk * 8 + lm + 4];
            const float fb0 = fbS[kk * 8 + lm];
            const float fb4 = fbS[kk * 8 + lm + 4];

            // B fragments: 4 x LDS.128, seg = kk*32 + lane
            uint32_t bfr[16];
            #pragma unroll
            for (int v = 0; v < 4; ++v) {
                const uint32_t ba = hsb + (uint32_t)(kk * 32 + lane) * 80u + (uint32_t)v * 16u;
                asm volatile("ld.shared.v4.b32 {%0,%1,%2,%3}, [%4];"
                             : "=r"(bfr[v * 4]), "=r"(bfr[v * 4 + 1]),
                               "=r"(bfr[v * 4 + 2]), "=r"(bfr[v * 4 + 3])
                             : "r"(ba));
            }

            #pragma unroll
            for (int mt = 0; mt < 2; ++mt) {
                uint32_t au[4];
                #pragma unroll
                for (int kh = 0; kh < 2; ++kh) {
                    const float djv = kh ? dj4 : dj0;
                    const float fbv = kh ? fb4 : fb0;
                    #pragma unroll
                    for (int sel = 0; sel < 2; ++sel) {
                        float av;
                        const uint32_t aa = adjb
                            + (uint32_t)(mt * 16 + sel * 8 + lq) * 272u
                            + (uint32_t)(kk * 8 + lm + 4 * kh) * 4u;
                        asm volatile("ld.shared.f32 %0, [%1];" : "=f"(av) : "r"(aa));
                        const float tl = fmaf(C08L, av, cil[mt * 2 + sel] + djv);
                        const float w  = tl > 0.f ? ex2f(tl) : fbv;
                        au[sel + 2 * kh] = f2tf32(w);
                    }
                }
                #pragma unroll
                for (int nt = 0; nt < 8; ++nt) {
                    const uint32_t b0 = bfr[(nt >> 1) * 4 + (nt & 1) * 2];
                    const uint32_t b1 = bfr[(nt >> 1) * 4 + (nt & 1) * 2 + 1];
                    MMA_TF32(acc[mt][nt], au, b0, b1);
                }
            }
        }
        __syncthreads();
    }

    // epilogue: partial store (float2 per c-pair)
    float* __restrict__ pout = g_pout[ks] + ((size_t)b * Nn + i0 + wid * 32) * 64;
    #pragma unroll
    for (int mt = 0; mt < 2; ++mt) {
        #pragma unroll
        for (int nt = 0; nt < 8; ++nt) {
            const size_t base = (size_t)(mt * 16 + lq) * 64 + nt * 8 + 2 * lm;
            *(float2*)(pout + base)            = make_float2(acc[mt][nt][0], acc[mt][nt][1]);
            *(float2*)(pout + base + 8 * 64)   = make_float2(acc[mt][nt][2], acc[mt][nt][3]);
        }
    }
}

// ============================================================================
// Kernel 5: out = relu(sum of KSPLIT partials)
// ============================================================================
__global__ __launch_bounds__(256) void k_fin(float* __restrict__ out) {
    const int idx = (blockIdx.x * 256 + threadIdx.x) * 4;
    float4 r = *(const float4*)(&g_pout[0][idx]);
    #pragma unroll
    for (int s = 1; s < KSPLIT; ++s) {
        const float4 p = *(const float4*)(&g_pout[s][idx]);
        r.x += p.x; r.y += p.y; r.z += p.z; r.w += p.w;
    }
    r.x = fmaxf(r.x, 0.f);
    r.y = fmaxf(r.y, 0.f);
    r.z = fmaxf(r.z, 0.f);
    r.w = fmaxf(r.w, 0.f);
    *(float4*)(out + idx) = r;
}

// ============================================================================
extern "C" void kernel_launch(void* const* d_in, const int* in_sizes, int n_in,
                              void* d_out, int out_size) {
    const float *inp = nullptr, *adj = nullptr, *W = nullptr, *a = nullptr;
    for (int i = 0; i < n_in; ++i) {
        switch (in_sizes[i]) {
            case 1048576:  inp = (const float*)d_in[i]; break; // 4*4096*64
            case 67108864: adj = (const float*)d_in[i]; break; // 4*4096*4096
            case 4096:     W   = (const float*)d_in[i]; break; // 64*64
            case 128:      a   = (const float*)d_in[i]; break; // 128*1
            default: break;
        }
    }
    float* out = (float*)d_out;

    cudaFuncSetAttribute(k_main, cudaFuncAttributeMaxDynamicSharedMemorySize, SM_TOTAL);
    cudaFuncSetAttribute(k_main, cudaFuncAttributePreferredSharedMemoryCarveout, 100);

    k_prep<<<Bc * Nn / 4, 256>>>(inp, W, a);

    // Per-batch ordering: colsum primes L2 with this batch's 67MB adj slice;
    // k_main then re-reads it mostly from L2.
    for (int b = 0; b < Bc; ++b) {
        dim3 g2(Nn / 1024, ISPLIT);
        k_colsum<<<g2, 256>>>(adj, b);
        k_hpack<<<64, 256>>>(b);
        dim3 g4(Nn / TI, KSPLIT);
        k_main<<<g4, 128, SM_TOTAL>>>(adj, b);
    }

    k_fin<<<Bc * Nn * Ff / 1024, 256>>>(out);
}

// round 5
// speedup vs baseline: 1.3814x; 1.3814x over previous
#include <cuda_runtime.h>
#include <cstdint>

// Problem constants
#define Bc 4
#define Nn 4096
#define Ff 64
#define ISPLIT 64         // i-range splits for colsum
#define TI 256            // i-rows per block in k_main
#define JC 64             // k-chunk (j columns) per stage
#define KSPLIT 2
#define CPB (Nn / JC / KSPLIT)   // 32 chunks per block
#define LOG2E 1.4426950408889634f
#define C08L  (0.8f * LOG2E)

// ---------------- scratch (device globals; no allocation allowed) ----------
__device__ float g_h   [Bc * Nn * Ff];      // h = inp @ W
__device__ float g_hsP [Bc * 64 * 4096];    // packed tf32 hs per chunk (seg layout)
__device__ float g_fsrc[Bc * Nn];           // 0.2*log2e * f_src (per i)
__device__ float g_fdst[Bc * Nn];           // 0.2*log2e * f_dst (per j)
__device__ float g_part[ISPLIT][Bc * Nn];   // colsum partials
__device__ float g_fbf [Bc * Nn];           // 1.0 if colsum==0 else 0.0
__device__ float g_pout[KSPLIT][Bc * Nn * Ff]; // k-split partial outputs

// ---------------- helpers ---------------------------------------------------
__device__ __forceinline__ float ex2f(float x) {
    float r; asm("ex2.approx.f32 %0, %1;" : "=f"(r) : "f"(x)); return r;
}
__device__ __forceinline__ uint32_t f2tf32(float x) {
    uint32_t u; asm("cvt.rna.tf32.f32 %0, %1;" : "=r"(u) : "f"(x)); return u;
}
__device__ __forceinline__ uint32_t smem_u32(const void* p) {
    uint32_t a;
    asm("{ .reg .u64 t; cvta.to.shared.u64 t, %1; cvt.u32.u64 %0, t; }" : "=r"(a) : "l"(p));
    return a;
}
#define CPA16(dst, src) \
    asm volatile("cp.async.cg.shared.global [%0], [%1], 16;" :: "r"(dst), "l"(src))
#define MMA_TF32(c, a, b0, b1) \
    asm volatile("mma.sync.aligned.m16n8k8.row.col.f32.tf32.tf32.f32 " \
        "{%0,%1,%2,%3},{%4,%5,%6,%7},{%8,%9},{%0,%1,%2,%3};" \
        : "+f"((c)[0]), "+f"((c)[1]), "+f"((c)[2]), "+f"((c)[3]) \
        : "r"((a)[0]), "r"((a)[1]), "r"((a)[2]), "r"((a)[3]), "r"(b0), "r"(b1))

// smem byte offsets (dynamic smem, 16B aligned)
#define SM_ADJ   0u                    // 2 x 256*68*4 = 139264
#define SM_HS    139264u               // 2 x 256*20*4 = 40960
#define SM_DJ    180224u               // 2 x 256
#define SM_FB    180736u               // 2 x 256
#define SM_TOTAL 181248u

// ============================================================================
// Kernel 1: h = inp @ W ; fsrc/fdst = 0.2*log2e * (lrelu(h) @ a halves)
// ============================================================================
__global__ __launch_bounds__(256) void k_prep(const float* __restrict__ inp,
                                              const float* __restrict__ W,
                                              const float* __restrict__ a) {
    __shared__ float Ws[64 * 64];
    __shared__ float as[128];
    __shared__ float inps[4][64];
    __shared__ float redS[4][2], redD[4][2];

    const int t = threadIdx.x;
    const int rowBase = blockIdx.x * 4;

    #pragma unroll
    for (int k = 0; k < 16; ++k) Ws[t + k * 256] = W[t + k * 256];
    if (t < 128) as[t] = a[t];

    const int r = t >> 6;
    const int o = t & 63;
    inps[r][o] = inp[(size_t)(rowBase + r) * 64 + o];
    __syncthreads();

    float hv = 0.f;
    #pragma unroll
    for (int f = 0; f < 64; ++f) hv = fmaf(inps[r][f], Ws[f * 64 + o], hv);

    const int gRow = rowBase + r;
    g_h[(size_t)gRow * 64 + o] = hv;

    const float lh = hv > 0.f ? hv : 0.2f * hv;
    float ps = lh * as[o];
    float pd = lh * as[64 + o];
    #pragma unroll
    for (int off = 16; off > 0; off >>= 1) {
        ps += __shfl_xor_sync(0xffffffffu, ps, off);
        pd += __shfl_xor_sync(0xffffffffu, pd, off);
    }
    const int wh = (t >> 5) & 1;
    if ((t & 31) == 0) { redS[r][wh] = ps; redD[r][wh] = pd; }
    __syncthreads();
    if ((t & 63) == 0) {
        g_fsrc[gRow] = 0.2f * LOG2E * (redS[r][0] + redS[r][1]);
        g_fdst[gRow] = 0.2f * LOG2E * (redD[r][0] + redD[r][1]);
    }
}

// ============================================================================
// Kernel 2: colsum partials. p_ij = (t>0 ? 2^t : 0). grid (4, 64, 4).
// Select-form accumulation (FSEL, no guarded-add chain), unroll 16.
// ============================================================================
__global__ __launch_bounds__(256) void k_colsum(const float* __restrict__ adj) {
    const int b  = blockIdx.z;
    const int j  = (blockIdx.x * 256 + threadIdx.x) * 4;
    const int i0 = blockIdx.y * (Nn / ISPLIT);
    const float4 dj = *(const float4*)(g_fdst + b * Nn + j);
    const float* __restrict__ fs = g_fsrc + b * Nn + i0;
    const float* __restrict__ ap = adj + ((size_t)b * Nn + i0) * Nn + j;

    float4 sum = make_float4(0.f, 0.f, 0.f, 0.f);
    #pragma unroll 16
    for (int i = 0; i < Nn / ISPLIT; ++i) {
        const float ci = fs[i];
        const float4 a = *(const float4*)(ap + (size_t)i * Nn);
        const float t0 = fmaf(C08L, a.x, ci + dj.x);
        const float t1 = fmaf(C08L, a.y, ci + dj.y);
        const float t2 = fmaf(C08L, a.z, ci + dj.z);
        const float t3 = fmaf(C08L, a.w, ci + dj.w);
        sum.x += (t0 > 0.f) ? ex2f(t0) : 0.f;
        sum.y += (t1 > 0.f) ? ex2f(t1) : 0.f;
        sum.z += (t2 > 0.f) ? ex2f(t2) : 0.f;
        sum.w += (t3 > 0.f) ? ex2f(t3) : 0.f;
    }
    *(float4*)(&g_part[blockIdx.y][b * Nn + j]) = sum;
}

// ============================================================================
// Kernel 3: reduce partials; pack hs = h/colsum (tf32) into B-fragment layout.
// grid (64, Bc). 256 threads: t<64 lanes own j, 4 s-quarters summed via smem.
// ============================================================================
__global__ __launch_bounds__(256) void k_hpack() {
    __shared__ float sc[64];
    __shared__ float qsum[4][64];
    const int t = threadIdx.x;
    const int c = blockIdx.x;
    const int b = blockIdx.y;
    const int j0 = c * 64;

    {
        const int jl = t & 63;
        const int sq = t >> 6;          // s-quarter 0..3
        float cs = 0.f;
        #pragma unroll
        for (int s = 0; s < ISPLIT / 4; ++s)
            cs += g_part[sq * (ISPLIT / 4) + s][b * Nn + j0 + jl];
        qsum[sq][jl] = cs;
    }
    __syncthreads();
    if (t < 64) {
        const float cs = qsum[0][t] + qsum[1][t] + qsum[2][t] + qsum[3][t];
        sc[t] = cs > 0.f ? (1.f / cs) : (1.f / (float)Nn);
        g_fbf[b * Nn + j0 + t] = cs > 0.f ? 0.f : 1.f;
    }
    __syncthreads();

    float* __restrict__ dst = g_hsP + (size_t)(b * 64 + c) * 4096;
    #pragma unroll
    for (int r = 0; r < 16; ++r) {
        const int o = t + r * 256;
        const int s = o >> 4, i = o & 15;
        const int ks = s >> 5, n07 = (s >> 2) & 7, k3 = s & 3;
        const int nt = i >> 1, half = i & 1;
        const int jl = ks * 8 + k3 + 4 * half;
        const int f  = nt * 8 + n07;
        const float v = g_h[((size_t)(b * Nn) + j0 + jl) * 64 + f] * sc[jl];
        dst[o] = __uint_as_float(f2tf32(v));
    }
}

// ============================================================================
// Kernel 4 (hot): partial out = A_att @ hs via mma.sync tf32.
// TI=256 rows, 256 thr (8 warps x 32 rows), KSPLIT=2. grid (16, Bc, 2).
// ============================================================================
__device__ __forceinline__ void issue_chunk(uint32_t sm, int p,
                                            const float* __restrict__ adjB,
                                            const float* __restrict__ hsPb,
                                            const float* __restrict__ djB,
                                            const float* __restrict__ fbB,
                                            int cglob, int t) {
    const int j0 = cglob * JC;
    // adj tile: 256 rows x 64 cols, pad 68 floats (272B/row)
    const uint32_t adst = sm + SM_ADJ + (uint32_t)p * 69632u;
    #pragma unroll
    for (int q = 0; q < 16; ++q) {
        const int quad = t + q * 256;
        const int row = quad >> 4, c4 = quad & 15;
        CPA16(adst + (uint32_t)row * 272u + (uint32_t)c4 * 16u,
              adjB + (size_t)row * Nn + j0 + c4 * 4);
    }
    // hs packed: 256 segs x 16 floats, seg stride 20 floats (80B)
    const uint32_t hdst = sm + SM_HS + (uint32_t)p * 20480u;
    const float* __restrict__ hsrc = hsPb + (size_t)cglob * 4096;
    #pragma unroll
    for (int q = 0; q < 4; ++q) {
        const int quad = t + q * 256;
        const int s = quad >> 2, v = quad & 3;
        CPA16(hdst + (uint32_t)s * 80u + (uint32_t)v * 16u, hsrc + quad * 4);
    }
    if (t < 16)
        CPA16(sm + SM_DJ + (uint32_t)p * 256u + (uint32_t)t * 16u, djB + j0 + t * 4);
    else if (t < 32)
        CPA16(sm + SM_FB + (uint32_t)p * 256u + (uint32_t)(t - 16) * 16u,
              fbB + j0 + (t - 16) * 4);
}

__global__ __launch_bounds__(256) void k_main(const float* __restrict__ adj) {
    extern __shared__ char dsm[];
    const uint32_t sm = smem_u32(dsm);

    const int t    = threadIdx.x;
    const int wid  = t >> 5;
    const int lane = t & 31;
    const int lq   = lane >> 2;   // group id (0..7)
    const int lm   = lane & 3;    // thread-in-group
    const int b    = blockIdx.y;
    const int i0   = blockIdx.x * TI;
    const int ks   = blockIdx.z;
    const int c0g  = ks * CPB;    // first global chunk

    const float* __restrict__ adjB = adj + ((size_t)b * Nn + i0) * Nn;
    const float* __restrict__ hsPb = g_hsP + (size_t)b * 64 * 4096;
    const float* __restrict__ djB  = g_fdst + b * Nn;
    const float* __restrict__ fbB  = g_fbf  + b * Nn;

    // ci (pre-scaled by 0.2*log2e): rows i0 + 32*wid + 16*mt + 8*sel + lq
    float cil[4];
    #pragma unroll
    for (int k = 0; k < 4; ++k)
        cil[k] = g_fsrc[b * Nn + i0 + wid * 32 + (k >> 1) * 16 + (k & 1) * 8 + lq];

    float acc[2][8][4];
    #pragma unroll
    for (int mt = 0; mt < 2; ++mt)
        #pragma unroll
        for (int nt = 0; nt < 8; ++nt)
            #pragma unroll
            for (int q = 0; q < 4; ++q) acc[mt][nt][q] = 0.f;

    issue_chunk(sm, 0, adjB, hsPb, djB, fbB, c0g, t);
    asm volatile("cp.async.commit_group;" ::: "memory");

    const uint32_t adjW = sm + SM_ADJ + (uint32_t)(wid * 32) * 272u;

    for (int c = 0; c < CPB; ++c) {
        const int p = c & 1;
        if (c + 1 < CPB)
            issue_chunk(sm, p ^ 1, adjB, hsPb, djB, fbB, c0g + c + 1, t);
        asm volatile("cp.async.commit_group;" ::: "memory");
        asm volatile("cp.async.wait_group 1;" ::: "memory");
        __syncthreads();

        const uint32_t adjb = adjW + (uint32_t)p * 69632u;
        const uint32_t hsb  = sm + SM_HS + (uint32_t)p * 20480u;
        const float* djS = (const float*)(dsm + SM_DJ + p * 256);
        const float* fbS = (const float*)(dsm + SM_FB + p * 256);

        #pragma unroll
        for (int kk = 0; kk < 8; ++kk) {
            const float dj0 = djS[kk * 8 + lm];
            const float dj4 = djS[kk * 8 + lm + 4];
            const float fb0 = fbS[kk * 8 + lm];
            const float fb4 = fbS[kk * 8 + lm + 4];

            // B fragments: 4 x LDS.128, seg = kk*32 + lane
            uint32_t bfr[16];
            #pragma unroll
            for (int v = 0; v < 4; ++v) {
                const uint32_t ba = hsb + (uint32_t)(kk * 32 + lane) * 80u + (uint32_t)v * 16u;
                asm volatile("ld.shared.v4.b32 {%0,%1,%2,%3}, [%4];"
                             : "=r"(bfr[v * 4]), "=r"(bfr[v * 4 + 1]),
                               "=r"(bfr[v * 4 + 2]), "=r"(bfr[v * 4 + 3])
                             : "r"(ba));
            }

            #pragma unroll
            for (int mt = 0; mt < 2; ++mt) {
                uint32_t au[4];
                #pragma unroll
                for (int kh = 0; kh < 2; ++kh) {
                    const float djv = kh ? dj4 : dj0;
                    const float fbv = kh ? fb4 : fb0;
                    #pragma unroll
                    for (int sel = 0; sel < 2; ++sel) {
                        float av;
                        const uint32_t aa = adjb
                            + (uint32_t)(mt * 16 + sel * 8 + lq) * 272u
                            + (uint32_t)(kk * 8 + lm + 4 * kh) * 4u;
                        asm volatile("ld.shared.f32 %0, [%1];" : "=f"(av) : "r"(aa));
                        const float tl = fmaf(C08L, av, cil[mt * 2 + sel] + djv);
                        const float w  = tl > 0.f ? ex2f(tl) : fbv;
                        au[sel + 2 * kh] = f2tf32(w);
                    }
                }
                #pragma unroll
                for (int nt = 0; nt < 8; ++nt) {
                    const uint32_t b0 = bfr[(nt >> 1) * 4 + (nt & 1) * 2];
                    const uint32_t b1 = bfr[(nt >> 1) * 4 + (nt & 1) * 2 + 1];
                    MMA_TF32(acc[mt][nt], au, b0, b1);
                }
            }
        }
        __syncthreads();
    }

    // epilogue: partial store (float2 per c-pair)
    float* __restrict__ pout = g_pout[ks] + ((size_t)(b * Nn) + i0 + wid * 32) * 64;
    #pragma unroll
    for (int mt = 0; mt < 2; ++mt) {
        #pragma unroll
        for (int nt = 0; nt < 8; ++nt) {
            const size_t base = (size_t)(mt * 16 + lq) * 64 + nt * 8 + 2 * lm;
            *(float2*)(pout + base)            = make_float2(acc[mt][nt][0], acc[mt][nt][1]);
            *(float2*)(pout + base + 8 * 64)   = make_float2(acc[mt][nt][2], acc[mt][nt][3]);
        }
    }
}

// ============================================================================
// Kernel 5: out = relu(p0 + p1)
// ============================================================================
__global__ __launch_bounds__(256) void k_fin(float* __restrict__ out) {
    const int idx = (blockIdx.x * 256 + threadIdx.x) * 4;
    const float4 p0 = *(const float4*)(&g_pout[0][idx]);
    const float4 p1 = *(const float4*)(&g_pout[1][idx]);
    float4 r;
    r.x = fmaxf(p0.x + p1.x, 0.f);
    r.y = fmaxf(p0.y + p1.y, 0.f);
    r.z = fmaxf(p0.z + p1.z, 0.f);
    r.w = fmaxf(p0.w + p1.w, 0.f);
    *(float4*)(out + idx) = r;
}

// ============================================================================
extern "C" void kernel_launch(void* const* d_in, const int* in_sizes, int n_in,
                              void* d_out, int out_size) {
    const float *inp = nullptr, *adj = nullptr, *W = nullptr, *a = nullptr;
    for (int i = 0; i < n_in; ++i) {
        switch (in_sizes[i]) {
            case 1048576:  inp = (const float*)d_in[i]; break; // 4*4096*64
            case 67108864: adj = (const float*)d_in[i]; break; // 4*4096*4096
            case 4096:     W   = (const float*)d_in[i]; break; // 64*64
            case 128:      a   = (const float*)d_in[i]; break; // 128*1
            default: break;
        }
    }
    float* out = (float*)d_out;

    cudaFuncSetAttribute(k_main, cudaFuncAttributeMaxDynamicSharedMemorySize, SM_TOTAL);

    k_prep<<<Bc * Nn / 4, 256>>>(inp, W, a);

    dim3 g2(Nn / 1024, ISPLIT, Bc);
    k_colsum<<<g2, 256>>>(adj);

    dim3 g3(64, Bc);
    k_hpack<<<g3, 256>>>();

    dim3 g4(Nn / TI, Bc, KSPLIT);
    k_main<<<g4, 256, SM_TOTAL>>>(adj);

    k_fin<<<Bc * Nn * Ff / 1024, 256>>>(out);
}

// round 6
// speedup vs baseline: 1.4990x; 1.0851x over previous
#include <cuda_runtime.h>
#include <cstdint>

// Problem constants
#define Bc 4
#define Nn 4096
#define Ff 64
#define ISPLIT 64         // i-range splits for colsum
#define TI 128            // i-rows per block in k_main
#define JC 64             // k-chunk (j columns) per stage
#define KSPLIT 2
#define CPB (Nn / JC / KSPLIT)   // 32 chunks per block
#define LOG2E 1.4426950408889634f
#define C08L  (0.8f * LOG2E)

// ---------------- scratch (device globals; no allocation allowed) ----------
__device__ float g_h   [Bc * Nn * Ff];      // h = inp @ W
__device__ float g_hsP [Bc * 64 * 4096];    // packed tf32 hs per chunk (seg layout)
__device__ float g_fsrc[Bc * Nn];           // 0.2*log2e * f_src (per i)
__device__ float g_fdst[Bc * Nn];           // 0.2*log2e * f_dst (per j)
__device__ float g_part[ISPLIT][Bc * Nn];   // colsum partials
__device__ float g_fbf [Bc * Nn];           // 1.0 if colsum==0 else 0.0
__device__ float g_pout[KSPLIT][Bc * Nn * Ff]; // k-split partial outputs

// ---------------- helpers ---------------------------------------------------
__device__ __forceinline__ float ex2f(float x) {
    float r; asm("ex2.approx.f32 %0, %1;" : "=f"(r) : "f"(x)); return r;
}
__device__ __forceinline__ uint32_t f2tf32(float x) {
    uint32_t u; asm("cvt.rna.tf32.f32 %0, %1;" : "=r"(u) : "f"(x)); return u;
}
__device__ __forceinline__ uint32_t smem_u32(const void* p) {
    uint32_t a;
    asm("{ .reg .u64 t; cvta.to.shared.u64 t, %1; cvt.u32.u64 %0, t; }" : "=r"(a) : "l"(p));
    return a;
}
__device__ __forceinline__ float4 ldcs4(const float* p) {
    float4 v;
    asm("ld.global.cs.v4.f32 {%0,%1,%2,%3}, [%4];"
        : "=f"(v.x), "=f"(v.y), "=f"(v.z), "=f"(v.w) : "l"(p));
    return v;
}
#define CPA16(dst, src) \
    asm volatile("cp.async.cg.shared.global [%0], [%1], 16;" :: "r"(dst), "l"(src))
#define MMA_TF32(c, a, b0, b1) \
    asm volatile("mma.sync.aligned.m16n8k8.row.col.f32.tf32.tf32.f32 " \
        "{%0,%1,%2,%3},{%4,%5,%6,%7},{%8,%9},{%0,%1,%2,%3};" \
        : "+f"((c)[0]), "+f"((c)[1]), "+f"((c)[2]), "+f"((c)[3]) \
        : "r"((a)[0]), "r"((a)[1]), "r"((a)[2]), "r"((a)[3]), "r"(b0), "r"(b1))

// smem byte offsets (dynamic smem, 16B aligned), TI=128
#define SM_ADJ   0u                    // 2 x 128*68*4 = 69632
#define SM_HS    69632u                // 2 x 256*20*4 = 40960
#define SM_DJ    110592u               // 2 x 256
#define SM_FB    111104u               // 2 x 256
#define SM_TOTAL 111616u               // x2 CTAs = 223232 <= 228KB

// ============================================================================
// Kernel 1: h = inp @ W ; fsrc/fdst = 0.2*log2e * (lrelu(h) @ a halves)
// ============================================================================
__global__ __launch_bounds__(256) void k_prep(const float* __restrict__ inp,
                                              const float* __restrict__ W,
                                              const float* __restrict__ a) {
    __shared__ float Ws[64 * 64];
    __shared__ float as[128];
    __shared__ float inps[4][64];
    __shared__ float redS[4][2], redD[4][2];

    const int t = threadIdx.x;
    const int rowBase = blockIdx.x * 4;

    #pragma unroll
    for (int k = 0; k < 16; ++k) Ws[t + k * 256] = W[t + k * 256];
    if (t < 128) as[t] = a[t];

    const int r = t >> 6;
    const int o = t & 63;
    inps[r][o] = inp[(size_t)(rowBase + r) * 64 + o];
    __syncthreads();

    float hv = 0.f;
    #pragma unroll
    for (int f = 0; f < 64; ++f) hv = fmaf(inps[r][f], Ws[f * 64 + o], hv);

    const int gRow = rowBase + r;
    g_h[(size_t)gRow * 64 + o] = hv;

    const float lh = hv > 0.f ? hv : 0.2f * hv;
    float ps = lh * as[o];
    float pd = lh * as[64 + o];
    #pragma unroll
    for (int off = 16; off > 0; off >>= 1) {
        ps += __shfl_xor_sync(0xffffffffu, ps, off);
        pd += __shfl_xor_sync(0xffffffffu, pd, off);
    }
    const int wh = (t >> 5) & 1;
    if ((t & 31) == 0) { redS[r][wh] = ps; redD[r][wh] = pd; }
    __syncthreads();
    if ((t & 63) == 0) {
        g_fsrc[gRow] = 0.2f * LOG2E * (redS[r][0] + redS[r][1]);
        g_fdst[gRow] = 0.2f * LOG2E * (redD[r][0] + redD[r][1]);
    }
}

// ============================================================================
// Kernel 2: colsum partials. p_ij = (t>0 ? 2^t : 0). grid (4, 64, 4).
// Streaming loads (.cs), select-form accumulation, unroll 16.
// ============================================================================
__global__ __launch_bounds__(256) void k_colsum(const float* __restrict__ adj) {
    const int b  = blockIdx.z;
    const int j  = (blockIdx.x * 256 + threadIdx.x) * 4;
    const int i0 = blockIdx.y * (Nn / ISPLIT);
    const float4 dj = *(const float4*)(g_fdst + b * Nn + j);
    const float* __restrict__ fs = g_fsrc + b * Nn + i0;
    const float* __restrict__ ap = adj + ((size_t)b * Nn + i0) * Nn + j;

    float4 sum = make_float4(0.f, 0.f, 0.f, 0.f);
    #pragma unroll 16
    for (int i = 0; i < Nn / ISPLIT; ++i) {
        const float ci = fs[i];
        const float4 a = ldcs4(ap + (size_t)i * Nn);
        const float t0 = fmaf(C08L, a.x, ci + dj.x);
        const float t1 = fmaf(C08L, a.y, ci + dj.y);
        const float t2 = fmaf(C08L, a.z, ci + dj.z);
        const float t3 = fmaf(C08L, a.w, ci + dj.w);
        sum.x += (t0 > 0.f) ? ex2f(t0) : 0.f;
        sum.y += (t1 > 0.f) ? ex2f(t1) : 0.f;
        sum.z += (t2 > 0.f) ? ex2f(t2) : 0.f;
        sum.w += (t3 > 0.f) ? ex2f(t3) : 0.f;
    }
    *(float4*)(&g_part[blockIdx.y][b * Nn + j]) = sum;
}

// ============================================================================
// Kernel 3: reduce partials; pack hs = h/colsum (tf32) into B-fragment layout.
// grid (64, Bc). 256 threads: 4 s-quarters summed via smem.
// ============================================================================
__global__ __launch_bounds__(256) void k_hpack() {
    __shared__ float sc[64];
    __shared__ float qsum[4][64];
    const int t = threadIdx.x;
    const int c = blockIdx.x;
    const int b = blockIdx.y;
    const int j0 = c * 64;

    {
        const int jl = t & 63;
        const int sq = t >> 6;          // s-quarter 0..3
        float cs = 0.f;
        #pragma unroll
        for (int s = 0; s < ISPLIT / 4; ++s)
            cs += g_part[sq * (ISPLIT / 4) + s][b * Nn + j0 + jl];
        qsum[sq][jl] = cs;
    }
    __syncthreads();
    if (t < 64) {
        const float cs = qsum[0][t] + qsum[1][t] + qsum[2][t] + qsum[3][t];
        sc[t] = cs > 0.f ? (1.f / cs) : (1.f / (float)Nn);
        g_fbf[b * Nn + j0 + t] = cs > 0.f ? 0.f : 1.f;
    }
    __syncthreads();

    float* __restrict__ dst = g_hsP + (size_t)(b * 64 + c) * 4096;
    #pragma unroll
    for (int r = 0; r < 16; ++r) {
        const int o = t + r * 256;
        const int s = o >> 4, i = o & 15;
        const int ks = s >> 5, n07 = (s >> 2) & 7, k3 = s & 3;
        const int nt = i >> 1, half = i & 1;
        const int jl = ks * 8 + k3 + 4 * half;
        const int f  = nt * 8 + n07;
        const float v = g_h[((size_t)(b * Nn) + j0 + jl) * 64 + f] * sc[jl];
        dst[o] = __uint_as_float(f2tf32(v));
    }
}

// ============================================================================
// Kernel 4 (hot): partial out = A_att @ hs via mma.sync tf32.
// TI=128 rows, 256 thr = 8 warps x 16 rows each. grid (32, Bc, 2).
// smem 111.6KB -> 2 CTAs/SM = 16 warps/SM.
// ============================================================================
__device__ __forceinline__ void issue_chunk(uint32_t sm, int p,
                                            const float* __restrict__ adjB,
                                            const float* __restrict__ hsPb,
                                            const float* __restrict__ djB,
                                            const float* __restrict__ fbB,
                                            int cglob, int t) {
    const int j0 = cglob * JC;
    // adj tile: 128 rows x 64 cols, pad 68 floats (272B/row)
    const uint32_t adst = sm + SM_ADJ + (uint32_t)p * 34816u;
    #pragma unroll
    for (int q = 0; q < 8; ++q) {
        const int quad = t + q * 256;
        const int row = quad >> 4, c4 = quad & 15;
        CPA16(adst + (uint32_t)row * 272u + (uint32_t)c4 * 16u,
              adjB + (size_t)row * Nn + j0 + c4 * 4);
    }
    // hs packed: 256 segs x 16 floats, seg stride 20 floats (80B)
    const uint32_t hdst = sm + SM_HS + (uint32_t)p * 20480u;
    const float* __restrict__ hsrc = hsPb + (size_t)cglob * 4096;
    #pragma unroll
    for (int q = 0; q < 4; ++q) {
        const int quad = t + q * 256;
        const int s = quad >> 2, v = quad & 3;
        CPA16(hdst + (uint32_t)s * 80u + (uint32_t)v * 16u, hsrc + quad * 4);
    }
    if (t < 16)
        CPA16(sm + SM_DJ + (uint32_t)p * 256u + (uint32_t)t * 16u, djB + j0 + t * 4);
    else if (t < 32)
        CPA16(sm + SM_FB + (uint32_t)p * 256u + (uint32_t)(t - 16) * 16u,
              fbB + j0 + (t - 16) * 4);
}

__global__ __launch_bounds__(256, 2) void k_main(const float* __restrict__ adj) {
    extern __shared__ char dsm[];
    const uint32_t sm = smem_u32(dsm);

    const int t    = threadIdx.x;
    const int wid  = t >> 5;      // 0..7, warp owns rows wid*16 .. wid*16+15
    const int lane = t & 31;
    const int lq   = lane >> 2;   // group id (0..7)
    const int lm   = lane & 3;    // thread-in-group
    const int b    = blockIdx.y;
    const int i0   = blockIdx.x * TI;
    const int ks   = blockIdx.z;
    const int c0g  = ks * CPB;    // first global chunk

    const float* __restrict__ adjB = adj + ((size_t)b * Nn + i0) * Nn;
    const float* __restrict__ hsPb = g_hsP + (size_t)b * 64 * 4096;
    const float* __restrict__ djB  = g_fdst + b * Nn;
    const float* __restrict__ fbB  = g_fbf  + b * Nn;

    // ci (pre-scaled by 0.2*log2e): rows i0 + wid*16 + sel*8 + lq
    float cil[2];
    #pragma unroll
    for (int sel = 0; sel < 2; ++sel)
        cil[sel] = g_fsrc[b * Nn + i0 + wid * 16 + sel * 8 + lq];

    float acc[8][4];
    #pragma unroll
    for (int nt = 0; nt < 8; ++nt)
        #pragma unroll
        for (int q = 0; q < 4; ++q) acc[nt][q] = 0.f;

    issue_chunk(sm, 0, adjB, hsPb, djB, fbB, c0g, t);
    asm volatile("cp.async.commit_group;" ::: "memory");

    const uint32_t adjW = sm + SM_ADJ + (uint32_t)(wid * 16) * 272u;

    for (int c = 0; c < CPB; ++c) {
        const int p = c & 1;
        if (c + 1 < CPB)
            issue_chunk(sm, p ^ 1, adjB, hsPb, djB, fbB, c0g + c + 1, t);
        asm volatile("cp.async.commit_group;" ::: "memory");
        asm volatile("cp.async.wait_group 1;" ::: "memory");
        __syncthreads();

        const uint32_t adjb = adjW + (uint32_t)p * 34816u;
        const uint32_t hsb  = sm + SM_HS + (uint32_t)p * 20480u;
        const float* djS = (const float*)(dsm + SM_DJ + p * 256);
        const float* fbS = (const float*)(dsm + SM_FB + p * 256);

        #pragma unroll
        for (int kk = 0; kk < 8; ++kk) {
            const float dj0 = djS[kk * 8 + lm];
            const float dj4 = djS[kk * 8 + lm + 4];
            const float fb0 = fbS[kk * 8 + lm];
            const float fb4 = fbS[kk * 8 + lm + 4];

            // B fragments: 4 x LDS.128, seg = kk*32 + lane
            uint32_t bfr[16];
            #pragma unroll
            for (int v = 0; v < 4; ++v) {
                const uint32_t ba = hsb + (uint32_t)(kk * 32 + lane) * 80u + (uint32_t)v * 16u;
                asm volatile("ld.shared.v4.b32 {%0,%1,%2,%3}, [%4];"
                             : "=r"(bfr[v * 4]), "=r"(bfr[v * 4 + 1]),
                               "=r"(bfr[v * 4 + 2]), "=r"(bfr[v * 4 + 3])
                             : "r"(ba));
            }

            // A fragment for this warp's 16-row tile
            uint32_t au[4];
            #pragma unroll
            for (int kh = 0; kh < 2; ++kh) {
                const float djv = kh ? dj4 : dj0;
                const float fbv = kh ? fb4 : fb0;
                #pragma unroll
                for (int sel = 0; sel < 2; ++sel) {
                    float av;
                    const uint32_t aa = adjb
                        + (uint32_t)(sel * 8 + lq) * 272u
                        + (uint32_t)(kk * 8 + lm + 4 * kh) * 4u;
                    asm volatile("ld.shared.f32 %0, [%1];" : "=f"(av) : "r"(aa));
                    const float tl = fmaf(C08L, av, cil[sel] + djv);
                    const float w  = tl > 0.f ? ex2f(tl) : fbv;
                    au[sel + 2 * kh] = f2tf32(w);
                }
            }
            #pragma unroll
            for (int nt = 0; nt < 8; ++nt) {
                const uint32_t b0 = bfr[(nt >> 1) * 4 + (nt & 1) * 2];
                const uint32_t b1 = bfr[(nt >> 1) * 4 + (nt & 1) * 2 + 1];
                MMA_TF32(acc[nt], au, b0, b1);
            }
        }
        __syncthreads();
    }

    // epilogue: partial store (float2 per c-pair)
    float* __restrict__ pout = g_pout[ks] + ((size_t)(b * Nn) + i0 + wid * 16) * 64;
    #pragma unroll
    for (int nt = 0; nt < 8; ++nt) {
        const size_t base = (size_t)lq * 64 + nt * 8 + 2 * lm;
        *(float2*)(pout + base)          = make_float2(acc[nt][0], acc[nt][1]);
        *(float2*)(pout + base + 8 * 64) = make_float2(acc[nt][2], acc[nt][3]);
    }
}

// ============================================================================
// Kernel 5: out = relu(p0 + p1)
// ============================================================================
__global__ __launch_bounds__(256) void k_fin(float* __restrict__ out) {
    const int idx = (blockIdx.x * 256 + threadIdx.x) * 4;
    const float4 p0 = *(const float4*)(&g_pout[0][idx]);
    const float4 p1 = *(const float4*)(&g_pout[1][idx]);
    float4 r;
    r.x = fmaxf(p0.x + p1.x, 0.f);
    r.y = fmaxf(p0.y + p1.y, 0.f);
    r.z = fmaxf(p0.z + p1.z, 0.f);
    r.w = fmaxf(p0.w + p1.w, 0.f);
    *(float4*)(out + idx) = r;
}

// ============================================================================
extern "C" void kernel_launch(void* const* d_in, const int* in_sizes, int n_in,
                              void* d_out, int out_size) {
    const float *inp = nullptr, *adj = nullptr, *W = nullptr, *a = nullptr;
    for (int i = 0; i < n_in; ++i) {
        switch (in_sizes[i]) {
            case 1048576:  inp = (const float*)d_in[i]; break; // 4*4096*64
            case 67108864: adj = (const float*)d_in[i]; break; // 4*4096*4096
            case 4096:     W   = (const float*)d_in[i]; break; // 64*64
            case 128:      a   = (const float*)d_in[i]; break; // 128*1
            default: break;
        }
    }
    float* out = (float*)d_out;

    cudaFuncSetAttribute(k_main, cudaFuncAttributeMaxDynamicSharedMemorySize, SM_TOTAL);

    k_prep<<<Bc * Nn / 4, 256>>>(inp, W, a);

    dim3 g2(Nn / 1024, ISPLIT, Bc);
    k_colsum<<<g2, 256>>>(adj);

    dim3 g3(64, Bc);
    k_hpack<<<g3, 256>>>();

    dim3 g4(Nn / TI, Bc, KSPLIT);
    k_main<<<g4, 256, SM_TOTAL>>>(adj);

    k_fin<<<Bc * Nn * Ff / 1024, 256>>>(out);
}